// round 17
// baseline (speedup 1.0000x reference)
#include <cuda_runtime.h>
#include <cuda.h>
#include <cuda_fp16.h>
#include <cstdint>

// ============================================================================
// SparseLinear: out[8192,4096] = x[8192,4096] @ (weight*mask)[4096,4096]^T
// fp16 staging + tcgen05 kind::f16 GEMM (sm_103a cubin pass), fp32 TMEM acc.
//
// R17: cg2 abandoned after two unobservable hangs (R15/R16). GEMM = exact
// R14 (cg1 + 4-CTA multicast quad, 7x32KB stages, warp-specialized): 255us
// proven. Prep streamlined: detect kernel deleted (per-block inline mask
// dtype detection from a 4KB window) and both converts fused -> one launch.
// ============================================================================

#define MDIM 8192
#define NDIM 4096
#define KDIM 4096
#define BM 256
#define BN 256
#define BK 32
#define NKT (KDIM / BK)   // 128
#define NT_TILES (NDIM / BN)              // 16
#define MT_TILES (MDIM / BM)              // 32
#define QN (NT_TILES / 2)                 // 8
#define QM (MT_TILES / 2)                 // 16
#define NQUADS (QN * QM)                  // 128
#define THREADS 288
#define STAGES 7

__device__ __align__(1024) __half g_A[(size_t)MDIM * KDIM];  // x as fp16
__device__ __align__(1024) __half g_B[(size_t)NDIM * KDIM];  // (w*mask) as fp16

// ---------------------------------------------------------------------------
// Helpers
// ---------------------------------------------------------------------------
__device__ __forceinline__ uint32_t smem_u32(const void* p) {
    uint32_t a;
    asm("{ .reg .u64 t; cvta.to.shared.u64 t, %1; cvt.u32.u64 %0, t; }"
        : "=r"(a) : "l"(p));
    return a;
}

// ---------------------------------------------------------------------------
// Fused prep: per-block inline mask-dtype detection + both conversions.
// Detection: scan first 4KB of mask (coalesced uint4). u8 bool: all byte
// positions ~10% nonzero. i32 0/1: only pos 0. f32 0/1.0f: only pos 2,3.
// Deterministic and identical in every block (same window).
// ---------------------------------------------------------------------------
#define NX4 ((size_t)MDIM * KDIM / 4)
#define NW4 ((size_t)NDIM * KDIM / 4)

__global__ void convert_all_kernel(const float* __restrict__ x,
                                   const float* __restrict__ w,
                                   const void* __restrict__ mask) {
    __shared__ int cnt[4];
    if (threadIdx.x < 4) cnt[threadIdx.x] = 0;
    __syncthreads();
    {
        uint4 v = ((const uint4*)mask)[threadIdx.x];   // 256 thr x 16B = 4KB
        uint32_t ws[4] = {v.x, v.y, v.z, v.w};
        int local[4] = {0, 0, 0, 0};
#pragma unroll
        for (int q = 0; q < 4; q++)
#pragma unroll
            for (int bpos = 0; bpos < 4; bpos++)
                local[bpos] += ((ws[q] >> (8 * bpos)) & 0xFF) ? 1 : 0;
#pragma unroll
        for (int j = 0; j < 4; j++)
            if (local[j]) atomicAdd(&cnt[j], local[j]);
    }
    __syncthreads();
    int mode;
    if (cnt[1] == 0 && cnt[2] == 0 && cnt[3] == 0) mode = 1;       // int32
    else if (cnt[0] == 0 && cnt[1] == 0)          mode = 2;       // float32
    else                                           mode = 0;       // uint8

    const size_t total = NX4 + NW4;
    size_t stride = (size_t)gridDim.x * blockDim.x;
    for (size_t j = (size_t)blockIdx.x * blockDim.x + threadIdx.x; j < total;
         j += stride) {
        if (j < NX4) {
            float4 v = ((const float4*)x)[j];
            __half2* o = (__half2*)g_A;
            o[2 * j + 0] = __floats2half2_rn(v.x, v.y);
            o[2 * j + 1] = __floats2half2_rn(v.z, v.w);
        } else {
            size_t i = j - NX4;
            float4 v = ((const float4*)w)[i];
            bool k0, k1, k2, k3;
            if (mode == 0) {
                uchar4 m = ((const uchar4*)mask)[i];
                k0 = m.x; k1 = m.y; k2 = m.z; k3 = m.w;
            } else if (mode == 1) {
                int4 m = ((const int4*)mask)[i];
                k0 = m.x; k1 = m.y; k2 = m.z; k3 = m.w;
            } else {
                float4 m = ((const float4*)mask)[i];
                k0 = m.x != 0.f; k1 = m.y != 0.f; k2 = m.z != 0.f; k3 = m.w != 0.f;
            }
            float a = k0 ? v.x : 0.0f;
            float b = k1 ? v.y : 0.0f;
            float c = k2 ? v.z : 0.0f;
            float d = k3 ? v.w : 0.0f;
            __half2* o = (__half2*)g_B;
            o[2 * i + 0] = __floats2half2_rn(a, b);
            o[2 * i + 1] = __floats2half2_rn(c, d);
        }
    }
}

// ---------------------------------------------------------------------------
// tcgen05-only helpers (compiled on the sm_103a cubin pass)
// ---------------------------------------------------------------------------
#if defined(__CUDA_ARCH_FEAT_SM103_ALL)
__device__ __forceinline__ bool elect_one() {
    uint32_t p;
    asm volatile(
        "{\n\t.reg .pred p;\n\t"
        "elect.sync _|p, 0xFFFFFFFF;\n\t"
        "selp.b32 %0, 1, 0, p;\n\t}"
        : "=r"(p));
    return p != 0;
}
__device__ __forceinline__ uint32_t ctarank() {
    uint32_t r;
    asm("mov.u32 %0, %%cluster_ctarank;" : "=r"(r));
    return r;
}
__device__ __forceinline__ void mbar_init(uint32_t mbar, uint32_t cnt) {
    asm volatile("mbarrier.init.shared.b64 [%0], %1;" :: "r"(mbar), "r"(cnt) : "memory");
}
__device__ __forceinline__ void mbar_wait(uint32_t mbar, uint32_t parity) {
    asm volatile(
        "{\n\t.reg .pred P1;\n\t"
        "WAIT_%=:\n\t"
        "mbarrier.try_wait.parity.acquire.cta.shared::cta.b64 P1, [%0], %1, 0x989680;\n\t"
        "@P1 bra.uni DONE_%=;\n\t"
        "bra.uni WAIT_%=;\n\t"
        "DONE_%=:\n\t}"
        :: "r"(mbar), "r"(parity) : "memory");
}
__device__ __forceinline__ void mbar_expect_tx(uint32_t mbar, uint32_t bytes) {
    asm volatile("mbarrier.arrive.expect_tx.shared.b64 _, [%0], %1;"
                 :: "r"(mbar), "r"(bytes) : "memory");
}
__device__ __forceinline__ void tma_load_2d_mc(uint32_t smem, const void* tm,
                                               int32_t x, int32_t y,
                                               uint32_t mbar, uint16_t mask) {
    asm volatile(
        "cp.async.bulk.tensor.2d.shared::cluster.global.tile."
        "mbarrier::complete_tx::bytes.multicast::cluster "
        "[%0], [%1, {%2, %3}], [%4], %5;"
        :: "r"(smem), "l"(tm), "r"(x), "r"(y), "r"(mbar), "h"(mask) : "memory");
}
// SW64 K-major descriptor: layout=4, version=1, SBO=32, LBO=1.
__device__ __forceinline__ uint64_t make_desc_sw64(uint32_t addr) {
    uint64_t d = (uint64_t(4) << 61) | (uint64_t(1) << 46) |
                 (uint64_t(32) << 32) | (uint64_t(1) << 16);
    return d | ((uint64_t)(addr >> 4) & 0x3FFF);
}
// idesc: dtype=F32, f16 inputs, N=256, M=128 per dispatch
#define MMA_IDESC ((1u << 4) | ((BN / 8) << 17) | ((128 / 16) << 24))
#endif

// ---------------------------------------------------------------------------
// GEMM kernel — persistent, warp-specialized, 4-CTA cluster multicast
// (byte-identical to R14's proven 255us configuration)
// ---------------------------------------------------------------------------
#define A_STAGE_BYTES (BM * 64)                        // 16KB (rows of 64B)
#define B_STAGE_BYTES (BN * 64)                        // 16KB
#define A_HALF (A_STAGE_BYTES / 2)                     // 8KB
#define B_HALF (B_STAGE_BYTES / 2)                     // 8KB
#define STAGE_BYTES (A_STAGE_BYTES + B_STAGE_BYTES)    // 32KB
#define SMEM_DYN_BYTES (STAGES * STAGE_BYTES + 1024)   // ~225KB

__global__ void __launch_bounds__(THREADS)
sparse_gemm_kernel(float* __restrict__ out,
                   const __grid_constant__ CUtensorMap tmA,
                   const __grid_constant__ CUtensorMap tmB) {
    extern __shared__ char dsmem[];
    const int tid = threadIdx.x;
    const int wid = tid >> 5;
    const int lid = tid & 31;

    const uint32_t tiles = (smem_u32(dsmem) + 1023u) & ~1023u;

#if defined(__CUDA_ARCH_FEAT_SM103_ALL)
    __shared__ uint64_t s_full[STAGES];   // TMA completion (expect_tx, cnt 1)
    __shared__ uint64_t s_mma[STAGES];    // MMA completion (4 mc commits)
    __shared__ uint32_t s_tmem_ptr;

    const uint32_t rank = ctarank();      // 0..3
    const int rm = (int)(rank >> 1);      // M offset within quad
    const int rn = (int)(rank & 1);       // N offset within quad
    const uint16_t maskA = (uint16_t)(0x3u << (2 * rm));   // A-sharing pair
    const uint16_t maskB = (uint16_t)(0x5u << rn);         // B-sharing pair
    const int NC = gridDim.x >> 2;        // clusters
    const int cc = blockIdx.x >> 2;       // cluster id

    if (wid == 0) {
        asm volatile("tcgen05.alloc.cta_group::1.sync.aligned.shared::cta.b32 [%0], %1;"
                     :: "r"(smem_u32(&s_tmem_ptr)), "r"(512) : "memory");
        asm volatile("tcgen05.relinquish_alloc_permit.cta_group::1.sync.aligned;");
    }
    if (tid == 0) {
#pragma unroll
        for (int s = 0; s < STAGES; s++) {
            mbar_init(smem_u32(&s_full[s]), 1);
            mbar_init(smem_u32(&s_mma[s]), 4);    // 4 multicast commits/slot
        }
        asm volatile("fence.proxy.async.shared::cta;" ::: "memory");
    }
    __syncthreads();
    // All cluster CTAs' barriers must be live before any multicast targets them.
    asm volatile("barrier.cluster.arrive.aligned;" ::: "memory");
    asm volatile("barrier.cluster.wait.aligned;" ::: "memory");

    uint32_t tmem;
    asm volatile("ld.shared.b32 %0, [%1];" : "=r"(tmem) : "r"(smem_u32(&s_tmem_ptr)));
    const uint32_t d0 = tmem;            // D rows [0,128)   TMEM cols [0,256)
    const uint32_t d1 = tmem + 256;      // D rows [128,256) TMEM cols [256,512)

    if (wid == 8) {
        // =================== PRODUCER warp (never joins bar 1) =============
        if (elect_one()) {
            int g = 0;
            for (int q = cc; q < NQUADS; q += NC) {
                const int mt = 2 * (q / QN) + rm;
                const int nt = 2 * (q % QN) + rn;
                for (int kt = 0; kt < NKT; kt++, g++) {
                    const int s = g % STAGES;
                    if (g >= STAGES)
                        mbar_wait(smem_u32(&s_mma[s]),
                                  (uint32_t)((g - STAGES) / STAGES) & 1u);
                    const uint32_t sb = tiles + s * STAGE_BYTES;
                    mbar_expect_tx(smem_u32(&s_full[s]), STAGE_BYTES);
                    tma_load_2d_mc(sb + rn * A_HALF, &tmA,
                                   kt * BK, mt * BM + rn * 128,
                                   smem_u32(&s_full[s]), maskA);
                    tma_load_2d_mc(sb + A_STAGE_BYTES + rm * B_HALF, &tmB,
                                   kt * BK, nt * BN + rm * 128,
                                   smem_u32(&s_full[s]), maskB);
                }
            }
        }
    } else {
        // ============== MMA issuer (warp 0) + epilogue (warps 0-7) ========
        int it = 0;
        for (int q = cc; q < NQUADS; q += NC, it++) {
            const int mt = 2 * (q / QN) + rm;
            const int nt = 2 * (q % QN) + rn;

            if (wid == 0 && elect_one()) {
                asm volatile("tcgen05.fence::after_thread_sync;" ::: "memory");
                for (int kt = 0; kt < NKT; kt++) {
                    const int g = it * NKT + kt;
                    const int s = g % STAGES;
                    mbar_wait(smem_u32(&s_full[s]), (uint32_t)(g / STAGES) & 1u);

                    const uint32_t stage_base = tiles + s * STAGE_BYTES;
                    uint64_t ad = make_desc_sw64(stage_base);
                    uint64_t ad2 = make_desc_sw64(stage_base + A_HALF);
                    uint64_t bd = make_desc_sw64(stage_base + A_STAGE_BYTES);
#pragma unroll
                    for (int s4 = 0; s4 < 2; s4++) {
                        uint32_t en = !(kt == 0 && s4 == 0);
                        asm volatile(
                            "{\n\t.reg .pred p;\n\t"
                            "setp.ne.u32 p, %4, 0;\n\t"
                            "tcgen05.mma.cta_group::1.kind::f16 [%0], %1, %2, %3, {%5,%5,%5,%5}, p;\n\t}"
                            :: "r"(d0), "l"(ad + 2 * s4), "l"(bd + 2 * s4),
                               "r"(MMA_IDESC), "r"(en), "r"(0u) : "memory");
                        asm volatile(
                            "{\n\t.reg .pred p;\n\t"
                            "setp.ne.u32 p, %4, 0;\n\t"
                            "tcgen05.mma.cta_group::1.kind::f16 [%0], %1, %2, %3, {%5,%5,%5,%5}, p;\n\t}"
                            :: "r"(d1), "l"(ad2 + 2 * s4), "l"(bd + 2 * s4),
                               "r"(MMA_IDESC), "r"(en), "r"(0u) : "memory");
                    }
                    asm volatile(
                        "tcgen05.commit.cta_group::1.mbarrier::arrive::one."
                        "shared::cluster.multicast::cluster.b64 [%0], %1;"
                        :: "r"(smem_u32(&s_mma[s])), "h"((uint16_t)0xF) : "memory");
                }
                const int gl = it * NKT + NKT - 1;
                mbar_wait(smem_u32(&s_mma[gl % STAGES]),
                          (uint32_t)(gl / STAGES) & 1u);
            }

            asm volatile("bar.sync 1, 256;" ::: "memory");
            asm volatile("tcgen05.fence::after_thread_sync;" ::: "memory");

            {
                const int h = wid >> 2;
                const int sw = wid & 3;
                const uint32_t dbase = tmem + h * 256;
                const int m = mt * BM + h * 128 + sw * 32 + lid;
                float* orow = out + (size_t)m * NDIM + nt * BN;
                uint32_t r[32];
#pragma unroll
                for (int c4 = 0; c4 < 8; c4++) {
                    asm volatile(
                        "tcgen05.ld.sync.aligned.32x32b.x32.b32 "
                        "{%0,%1,%2,%3,%4,%5,%6,%7,%8,%9,%10,%11,%12,%13,%14,%15,"
                        "%16,%17,%18,%19,%20,%21,%22,%23,%24,%25,%26,%27,%28,%29,%30,%31}, [%32];"
                        : "=r"(r[0]), "=r"(r[1]), "=r"(r[2]), "=r"(r[3]),
                          "=r"(r[4]), "=r"(r[5]), "=r"(r[6]), "=r"(r[7]),
                          "=r"(r[8]), "=r"(r[9]), "=r"(r[10]), "=r"(r[11]),
                          "=r"(r[12]), "=r"(r[13]), "=r"(r[14]), "=r"(r[15]),
                          "=r"(r[16]), "=r"(r[17]), "=r"(r[18]), "=r"(r[19]),
                          "=r"(r[20]), "=r"(r[21]), "=r"(r[22]), "=r"(r[23]),
                          "=r"(r[24]), "=r"(r[25]), "=r"(r[26]), "=r"(r[27]),
                          "=r"(r[28]), "=r"(r[29]), "=r"(r[30]), "=r"(r[31])
                        : "r"(dbase + c4 * 32));
                    asm volatile("tcgen05.wait::ld.sync.aligned;" ::: "memory");
                    float4* p = (float4*)(orow + c4 * 32);
#pragma unroll
                    for (int qq = 0; qq < 8; qq++)
                        p[qq] = make_float4(__uint_as_float(r[4 * qq + 0]),
                                            __uint_as_float(r[4 * qq + 1]),
                                            __uint_as_float(r[4 * qq + 2]),
                                            __uint_as_float(r[4 * qq + 3]));
                }
                asm volatile("tcgen05.fence::before_thread_sync;" ::: "memory");
            }
            asm volatile("bar.sync 1, 256;" ::: "memory");
        }
    }

    __syncthreads();   // all 9 warps
    asm volatile("barrier.cluster.arrive.aligned;" ::: "memory");
    asm volatile("barrier.cluster.wait.aligned;" ::: "memory");
    if (wid == 0)
        asm volatile("tcgen05.dealloc.cta_group::1.sync.aligned.b32 %0, %1;"
                     :: "r"(tmem), "r"(512));

#else
    // ===== fallback (compute_103 PTX pass only; cubin path always used) ====
    (void)tiles;
    for (int t = blockIdx.x; t < NQUADS * 4; t += gridDim.x) {
        const int mt = t / NT_TILES;
        const int nt = t % NT_TILES;
        for (int idx = tid; idx < BM * BN; idx += THREADS) {
            int r = idx / BN, c = idx % BN;
            const __half* a = g_A + (size_t)(mt * BM + r) * KDIM;
            const __half* b = g_B + (size_t)(nt * BN + c) * KDIM;
            float s = 0.0f;
            for (int k = 0; k < KDIM; k++)
                s += __half2float(a[k]) * __half2float(b[k]);
            out[(size_t)(mt * BM + r) * NDIM + nt * BN + c] = s;
        }
    }
#endif
}

// ---------------------------------------------------------------------------
// Launch
// ---------------------------------------------------------------------------
typedef CUresult (*PFN_tmEncode)(
    CUtensorMap*, CUtensorMapDataType, cuuint32_t, void*,
    const cuuint64_t*, const cuuint64_t*, const cuuint32_t*, const cuuint32_t*,
    CUtensorMapInterleave, CUtensorMapSwizzle, CUtensorMapL2promotion,
    CUtensorMapFloatOOBfill);

extern "C" void kernel_launch(void* const* d_in, const int* in_sizes, int n_in,
                              void* d_out, int out_size) {
    const float* x = (const float*)d_in[0];
    const float* w = (const float*)d_in[1];
    const void* mask = d_in[2];
    float* out = (float*)d_out;

    void* pA = nullptr;
    void* pB = nullptr;
    cudaGetSymbolAddress(&pA, g_A);
    cudaGetSymbolAddress(&pB, g_B);

    void* fn = nullptr;
    cudaDriverEntryPointQueryResult qres;
    cudaGetDriverEntryPoint("cuTensorMapEncodeTiled", &fn,
                            cudaEnableDefault, &qres);
    PFN_tmEncode tmEncode = (PFN_tmEncode)fn;

    CUtensorMap tmA, tmB;
    {
        cuuint64_t dims[2] = {(cuuint64_t)KDIM, (cuuint64_t)MDIM};
        cuuint64_t strides[1] = {(cuuint64_t)KDIM * 2};
        cuuint32_t box[2] = {(cuuint32_t)BK, 128};   // 32 x 128 half-tile
        cuuint32_t estr[2] = {1, 1};
        tmEncode(&tmA, CU_TENSOR_MAP_DATA_TYPE_FLOAT16, 2, pA,
                 dims, strides, box, estr,
                 CU_TENSOR_MAP_INTERLEAVE_NONE, CU_TENSOR_MAP_SWIZZLE_64B,
                 CU_TENSOR_MAP_L2_PROMOTION_L2_128B,
                 CU_TENSOR_MAP_FLOAT_OOB_FILL_NONE);
    }
    {
        cuuint64_t dims[2] = {(cuuint64_t)KDIM, (cuuint64_t)NDIM};
        cuuint64_t strides[1] = {(cuuint64_t)KDIM * 2};
        cuuint32_t box[2] = {(cuuint32_t)BK, 128};   // 32 x 128 half-tile
        cuuint32_t estr[2] = {1, 1};
        tmEncode(&tmB, CU_TENSOR_MAP_DATA_TYPE_FLOAT16, 2, pB,
                 dims, strides, box, estr,
                 CU_TENSOR_MAP_INTERLEAVE_NONE, CU_TENSOR_MAP_SWIZZLE_64B,
                 CU_TENSOR_MAP_L2_PROMOTION_L2_128B,
                 CU_TENSOR_MAP_FLOAT_OOB_FILL_NONE);
    }

    cudaFuncSetAttribute(sparse_gemm_kernel,
                         cudaFuncAttributeMaxDynamicSharedMemorySize,
                         SMEM_DYN_BYTES);

    // Single fused prep launch (inline mask detection, both conversions).
    convert_all_kernel<<<4736, 256>>>(x, w, mask);

    // 128 CTAs = 32 clusters of 4 (all resident; csz-4 active limit is 132).
    cudaLaunchConfig_t config = {};
    config.gridDim = dim3(128, 1, 1);
    config.blockDim = dim3(THREADS, 1, 1);
    config.dynamicSmemBytes = SMEM_DYN_BYTES;
    cudaLaunchAttribute attrs[1];
    attrs[0].id = cudaLaunchAttributeClusterDimension;
    attrs[0].val.clusterDim.x = 4;
    attrs[0].val.clusterDim.y = 1;
    attrs[0].val.clusterDim.z = 1;
    config.attrs = attrs;
    config.numAttrs = 1;
    cudaLaunchKernelEx(&config, sparse_gemm_kernel, out, tmA, tmB);
}